// round 15
// baseline (speedup 1.0000x reference)
#include <cuda_runtime.h>
#include <cuda_fp16.h>
#include <cstdint>

// GraphConv: out = relu( ((A @ X + X) / (rowsum(A)+1)) @ W )
// A: [4,4096,4096] f32, X: [4,4096,128] f32, W: [128,128] f32, out f32.
// fp16 mma.sync m16n8k16; WARP-SPECIALIZED: 8 producer + 8 consumer warps,
// 3-stage A+B pipeline synced with named barriers.

#define Bn 4
#define Nn 4096
#define Fn 128
#define KT 64
#define NTILES (Nn / KT)   // 64
#define STAGES 3
#define NTHR 512

// device scratch: X^T per batch [f][k] fp16, W^T [n][k] fp16
__device__ __align__(256) __half Xt_g[(size_t)Bn * Fn * Nn];
__device__ __align__(256) __half Wt_g[Fn * Fn];

// smem layout (bytes):
//  stages 3 x (A 16KB + B 16KB) @ 0   (Ys 2 x 16KB reuses stage0 post-mainloop)
//  Ws   2 x 16384 @ 98304
//  degp 128*16*4  @ 131072
#define STAGE_B 32768
#define WS_OFF  98304
#define YS_OFF  0
#define DEG_OFF 131072
#define SMEM_TOTAL (DEG_OFF + 8192)   // 139264

#define SW(x) ((x) ^ (((x) >> 3) & 0x70))

__device__ __forceinline__ uint32_t smem_u32(const void* p) {
    uint32_t a;
    asm("{ .reg .u64 t; cvta.to.shared.u64 t, %1; cvt.u32.u64 %0, t; }" : "=r"(a) : "l"(p));
    return a;
}
__device__ __forceinline__ void cp16(uint32_t dst, const void* src) {
    asm volatile("cp.async.cg.shared.global [%0], [%1], 16;" :: "r"(dst), "l"(src) : "memory");
}
__device__ __forceinline__ void ldsm4(uint32_t* r, uint32_t a) {
    asm volatile("ldmatrix.sync.aligned.m8n8.x4.shared.b16 {%0,%1,%2,%3}, [%4];"
                 : "=r"(r[0]), "=r"(r[1]), "=r"(r[2]), "=r"(r[3]) : "r"(a));
}
__device__ __forceinline__ void mma16(float* c, const uint32_t* a, const uint32_t* b) {
    asm volatile(
        "mma.sync.aligned.m16n8k16.row.col.f32.f16.f16.f32 "
        "{%0,%1,%2,%3},{%4,%5,%6,%7},{%8,%9},{%0,%1,%2,%3};"
        : "+f"(c[0]), "+f"(c[1]), "+f"(c[2]), "+f"(c[3])
        : "r"(a[0]), "r"(a[1]), "r"(a[2]), "r"(a[3]), "r"(b[0]), "r"(b[1]));
}
__device__ __forceinline__ uint32_t packh2(float a, float b) {
    __half2 h = __floats2half2_rn(a, b);
    return *(uint32_t*)&h;
}
__device__ __forceinline__ void bar_sync(int id) {
    asm volatile("bar.sync %0, %1;" :: "r"(id), "r"(512u) : "memory");
}
__device__ __forceinline__ void bar_arrive(int id) {
    asm volatile("bar.arrive %0, %1;" :: "r"(id), "r"(512u) : "memory");
}

// ===================== fused prep kernel =====================
__global__ void prep_fused(const float* __restrict__ X, const float* __restrict__ W) {
    __shared__ float t[32][33];
    int tx = threadIdx.x, ty = threadIdx.y;   // 32 x 8
    if (blockIdx.z < Bn) {
        int b = blockIdx.z;
        int bk = blockIdx.x * 32;
        int bn = blockIdx.y * 32;
        const float* Xb = X + (size_t)b * Nn * Fn;
        __half* Xtb = Xt_g + (size_t)b * Fn * Nn;
#pragma unroll
        for (int i = 0; i < 4; i++)
            t[ty + i * 8][tx] = Xb[(size_t)(bk + ty + i * 8) * Fn + bn + tx];
        __syncthreads();
#pragma unroll
        for (int i = 0; i < 4; i++)
            Xtb[(size_t)(bn + ty + i * 8) * Nn + bk + tx] = __float2half_rn(t[tx][ty + i * 8]);
    } else {
        if (blockIdx.x >= 4 || blockIdx.y >= 4) return;
        int bk = blockIdx.x * 32, bn = blockIdx.y * 32;
#pragma unroll
        for (int i = 0; i < 4; i++)
            t[ty + i * 8][tx] = W[(size_t)(bk + ty + i * 8) * Fn + bn + tx];
        __syncthreads();
#pragma unroll
        for (int i = 0; i < 4; i++)
            Wt_g[(size_t)(bn + ty + i * 8) * Fn + bk + tx] = __float2half_rn(t[tx][ty + i * 8]);
    }
}

// ===================== main kernel =====================
__global__ __launch_bounds__(NTHR, 1)
void graphconv_mma_kernel(const float* __restrict__ A,
                          const float* __restrict__ X,
                          float* __restrict__ out)
{
    extern __shared__ char smem[];
    const uint32_t sb = smem_u32(smem);
    const int tid = threadIdx.x;
    const int w = tid >> 5, L = tid & 31;
    const int b = blockIdx.y, r0 = blockIdx.x * 128;

    const int g = L >> 2, tg = L & 3;
    // ldsm lane offsets (fp16, 128B rows)
    const int arow = L & 15;
    const int achk = (L >> 4) * 16;
    const int brow = (L & 7) + ((L >> 4) << 3);
    const int bchk = ((L >> 3) & 1) * 16;

    const float* Abase = A + ((size_t)b * Nn + r0) * Nn;
    const __half* Xth  = Xt_g + (size_t)b * Fn * Nn;
    float* degp = (float*)(smem + DEG_OFF);   // [128 rows][16 chunks]

    float acc[16][4];   // consumer accumulators (m64 x n32)
#pragma unroll
    for (int i = 0; i < 16; i++)
#pragma unroll
        for (int j = 0; j < 4; j++) acc[i][j] = 0.0f;

    // consumer mainloop tile position: m64 x n32, warps 2(m) x 4(n)
    const int mw = (w >> 2) * 64;
    const int nw = (w & 3) * 32;

    if (w < 8) {
        // ================= CONSUMERS =================
        for (int t = 0; t < NTILES; t++) {
            int s = t - (t >= 48 ? 48 : (t >= 24 ? 24 : 0));  // t % 3 cheap
            s = t % 3;
            bar_sync(1 + s);             // wait full
            uint32_t aA = sb + s * STAGE_B;
            uint32_t aB = aA + 16384;
#pragma unroll
            for (int kc = 0; kc < 4; kc++) {
                const int koff = kc * 32;
                uint32_t af[4][4];
#pragma unroll
                for (int mt = 0; mt < 4; mt++)
                    ldsm4(af[mt], aA + SW((mw + mt * 16 + arow) * 128 + koff + achk));
                uint32_t bf[4][2];
#pragma unroll
                for (int np = 0; np < 2; np++) {
                    uint32_t r[4];
                    ldsm4(r, aB + SW((nw + np * 16 + brow) * 128 + koff + bchk));
                    bf[np * 2][0] = r[0]; bf[np * 2][1] = r[1];
                    bf[np * 2 + 1][0] = r[2]; bf[np * 2 + 1][1] = r[3];
                }
#pragma unroll
                for (int mt = 0; mt < 4; mt++)
#pragma unroll
                    for (int nt = 0; nt < 4; nt++)
                        mma16(acc[mt * 4 + nt], af[mt], bf[nt]);
            }
            if (t + STAGES < NTILES) bar_arrive(4 + s);   // release stage
        }
    } else {
        // ================= PRODUCERS =================
        const int ptid = tid - 256;
        const int lrow = ptid >> 4;   // 0..15 (+16i), 16 threads per row
        const int lcol = ptid & 15;   // 16B unit
        const float* Aldg = Abase + (size_t)lrow * Nn + lcol * 4;
        float dega[8] = {0, 0, 0, 0, 0, 0, 0, 0};
        float4 aq[8];

        // prefetch A tile 0
#pragma unroll
        for (int i = 0; i < 8; i++)
            aq[i] = *(const float4*)(Aldg + (size_t)(16 * i) * Nn);

        for (int t = 0; t < NTILES; t++) {
            int s = t % 3;
            if (t >= STAGES) bar_sync(4 + s);    // wait stage empty
            uint32_t base = sb + s * STAGE_B;
            // store A tile t (from aq), accumulate exact deg
#pragma unroll
            for (int i = 0; i < 8; i++) {
                float4 v = aq[i];
                dega[i] += (v.x + v.y) + (v.z + v.w);
                uint32_t d = base + SW((lrow + 16 * i) * 128 + lcol * 8);
                asm volatile("st.shared.v2.b32 [%0], {%1,%2};"
                    :: "r"(d), "r"(packh2(v.x, v.y)), "r"(packh2(v.z, v.w)) : "memory");
            }
            // prefetch A tile t+1 (latency hidden under cp wait)
            if (t + 1 < NTILES) {
#pragma unroll
                for (int i = 0; i < 8; i++)
                    aq[i] = *(const float4*)(Aldg + (size_t)(16 * i) * Nn + (t + 1) * KT);
            }
            // B tile t via cp.async
            const int k0 = t * KT;
#pragma unroll
            for (int i = 0; i < 4; i++) {
                int c = ptid + i * 256;     // 0..1023
                int n = c >> 3, j = c & 7;
                cp16(base + 16384 + SW(n * 128 + j * 16),
                     Xth + (size_t)n * Nn + k0 + j * 8);
            }
            asm volatile("cp.async.commit_group;" ::: "memory");
            asm volatile("cp.async.wait_group 0;" ::: "memory");
            bar_arrive(1 + s);    // stage full
        }
        // deg partials -> smem
#pragma unroll
        for (int i = 0; i < 8; i++)
            degp[(lrow + 16 * i) * 16 + lcol] = dega[i];
    }

    // ---- stage W^T (all threads) ----
#pragma unroll
    for (int i = 0; i < 4; i++) {
        int c = tid + i * NTHR;         // 0..2047 chunks of 8 halves
        int n = c >> 4, j = c & 15, kt = j >> 3, jj = j & 7;
        cp16(sb + WS_OFF + kt * 16384 + SW(n * 128 + jj * 16),
             Wt_g + (size_t)n * Fn + j * 8);
    }
    asm volatile("cp.async.commit_group;" ::: "memory");
    __syncthreads();   // mainloops done; degp visible; stage0 free for Ys

    // ---- y = (ax + X) / (deg + 1) -> fp16 smem (consumers hold acc) ----
    if (w < 8) {
#pragma unroll
        for (int mt = 0; mt < 4; mt++) {
            int m1 = mw + mt * 16 + g, m2 = m1 + 8;
            float s1 = 0.0f, s2 = 0.0f;
#pragma unroll
            for (int j = 0; j < 16; j++) { s1 += degp[m1 * 16 + j]; s2 += degp[m2 * 16 + j]; }
            float r1 = 1.0f / (s1 + 1.0f);
            float r2 = 1.0f / (s2 + 1.0f);
            const float* x1 = X + ((size_t)b * Nn + r0 + m1) * Fn;
            const float* x2 = X + ((size_t)b * Nn + r0 + m2) * Fn;
#pragma unroll
            for (int nt = 0; nt < 4; nt++) {
                int n = nw + nt * 8 + 2 * tg;
                float* c = acc[mt * 4 + nt];
                float2 xa = *(const float2*)(x1 + n);
                float2 xb = *(const float2*)(x2 + n);
                uint32_t y01 = packh2((c[0] + xa.x) * r1, (c[1] + xa.y) * r1);
                uint32_t y23 = packh2((c[2] + xb.x) * r2, (c[3] + xb.y) * r2);
                uint32_t base = sb + YS_OFF + (n >> 6) * 16384;
                asm volatile("st.shared.b32 [%0], %1;"
                             :: "r"(base + SW(m1 * 128 + (n & 63) * 2)), "r"(y01) : "memory");
                asm volatile("st.shared.b32 [%0], %1;"
                             :: "r"(base + SW(m2 * 128 + (n & 63) * 2)), "r"(y23) : "memory");
            }
        }
    }
    asm volatile("cp.async.wait_group 0;" ::: "memory");
    __syncthreads();

    // ---- second GEMM: z = y @ W (M=128,N=128,K=128), m32n32 x 16 warps ----
    const int mw2 = (w >> 2) * 32;
    const int nw2 = (w & 3) * 32;
    float acc2[8][4];
#pragma unroll
    for (int i = 0; i < 8; i++)
#pragma unroll
        for (int j = 0; j < 4; j++) acc2[i][j] = 0.0f;

#pragma unroll
    for (int kt = 0; kt < 2; kt++) {
        uint32_t aY = sb + YS_OFF + kt * 16384;
        uint32_t aW = sb + WS_OFF + kt * 16384;
#pragma unroll
        for (int kc = 0; kc < 4; kc++) {
            const int koff = kc * 32;
            uint32_t af[2][4];
#pragma unroll
            for (int mt = 0; mt < 2; mt++)
                ldsm4(af[mt], aY + SW((mw2 + mt * 16 + arow) * 128 + koff + achk));
            uint32_t bf[4][2];
#pragma unroll
            for (int np = 0; np < 2; np++) {
                uint32_t r[4];
                ldsm4(r, aW + SW((nw2 + np * 16 + brow) * 128 + koff + bchk));
                bf[np * 2][0] = r[0]; bf[np * 2][1] = r[1];
                bf[np * 2 + 1][0] = r[2]; bf[np * 2 + 1][1] = r[3];
            }
#pragma unroll
            for (int mt = 0; mt < 2; mt++)
#pragma unroll
                for (int nt = 0; nt < 4; nt++)
                    mma16(acc2[mt * 4 + nt], af[mt], bf[nt]);
        }
    }

    // ---- relu + store ----
#pragma unroll
    for (int mt = 0; mt < 2; mt++) {
        int m1 = mw2 + mt * 16 + g, m2 = m1 + 8;
        float* o1 = out + ((size_t)b * Nn + r0 + m1) * Fn;
        float* o2 = out + ((size_t)b * Nn + r0 + m2) * Fn;
#pragma unroll
        for (int nt = 0; nt < 4; nt++) {
            int n = nw2 + nt * 8 + 2 * tg;
            float* c = acc2[mt * 4 + nt];
            *(float2*)(o1 + n) = make_float2(fmaxf(c[0], 0.0f), fmaxf(c[1], 0.0f));
            *(float2*)(o2 + n) = make_float2(fmaxf(c[2], 0.0f), fmaxf(c[3], 0.0f));
        }
    }
}

// ===================== launch =====================
extern "C" void kernel_launch(void* const* d_in, const int* in_sizes, int n_in,
                              void* d_out, int out_size)
{
    const float* A = (const float*)d_in[0];
    const float* X = (const float*)d_in[1];
    const float* W = (const float*)d_in[2];
    float* out = (float*)d_out;

    static bool attr_set = false;
    if (!attr_set) {
        cudaFuncSetAttribute(graphconv_mma_kernel,
                             cudaFuncAttributeMaxDynamicSharedMemorySize, SMEM_TOTAL);
        attr_set = true;
    }

    dim3 tb(32, 8);
    prep_fused<<<dim3(Nn / 32, Fn / 32, Bn + 1), tb>>>(X, W);

    dim3 grid(Nn / 128, Bn);
    graphconv_mma_kernel<<<grid, NTHR, SMEM_TOTAL>>>(A, X, out);
}

// round 16
// speedup vs baseline: 1.4268x; 1.4268x over previous
#include <cuda_runtime.h>
#include <cuda_fp16.h>
#include <cstdint>

// GraphConv: out = relu( ((A @ X + X) / (rowsum(A)+1)) @ W )
// A: [4,4096,4096] f32, X: [4,4096,128] f32, W: [128,128] f32, out f32.
// fp16 mma.sync m16n8k16; R7 main kernel verbatim (16 warps m32n32, KT=64,
// 4-stage cp.async). Prep consolidated: 640 blocks instead of 2048.

#define Bn 4
#define Nn 4096
#define Fn 128
#define KT 64
#define NTILES (Nn / KT)   // 64
#define BSTAGES 4
#define NTHR 512

// device scratch: X^T per batch [f][k] fp16, W^T [n][k] fp16
__device__ __align__(256) __half Xt_g[(size_t)Bn * Fn * Nn];
__device__ __align__(256) __half Wt_g[Fn * Fn];

// smem layout (bytes):
//  Abuf 2 x 16384 @ 0       (Ys 2 x 16384 reuses @0 post-mainloop)
//  Bstg 4 x 16384 @ 32768   (Ws 2 x 16384 reuses stages 0-1 post-mainloop)
//  degp 128*16*4  @ 98304
#define AB_OFF  0
#define BS_OFF  32768
#define WS_OFF  32768
#define YS_OFF  0
#define DEG_OFF 98304
#define SMEM_TOTAL (DEG_OFF + 8192)

#define SW(x) ((x) ^ (((x) >> 3) & 0x70))

__device__ __forceinline__ uint32_t smem_u32(const void* p) {
    uint32_t a;
    asm("{ .reg .u64 t; cvta.to.shared.u64 t, %1; cvt.u32.u64 %0, t; }" : "=r"(a) : "l"(p));
    return a;
}
__device__ __forceinline__ void cp16(uint32_t dst, const void* src) {
    asm volatile("cp.async.cg.shared.global [%0], [%1], 16;" :: "r"(dst), "l"(src) : "memory");
}
__device__ __forceinline__ void ldsm4(uint32_t* r, uint32_t a) {
    asm volatile("ldmatrix.sync.aligned.m8n8.x4.shared.b16 {%0,%1,%2,%3}, [%4];"
                 : "=r"(r[0]), "=r"(r[1]), "=r"(r[2]), "=r"(r[3]) : "r"(a));
}
__device__ __forceinline__ void mma16(float* c, const uint32_t* a, const uint32_t* b) {
    asm volatile(
        "mma.sync.aligned.m16n8k16.row.col.f32.f16.f16.f32 "
        "{%0,%1,%2,%3},{%4,%5,%6,%7},{%8,%9},{%0,%1,%2,%3};"
        : "+f"(c[0]), "+f"(c[1]), "+f"(c[2]), "+f"(c[3])
        : "r"(a[0]), "r"(a[1]), "r"(a[2]), "r"(a[3]), "r"(b[0]), "r"(b[1]));
}
__device__ __forceinline__ uint32_t packh2(float a, float b) {
    __half2 h = __floats2half2_rn(a, b);
    return *(uint32_t*)&h;
}

// ===================== consolidated prep kernel =====================
// z in [0, Bn): transpose X batch z -> Xt_g fp16 (4 k-subtiles per block).
// z == Bn: transpose W -> Wt_g fp16 (blockIdx.x == 0 only; 4 bk-subtiles).
__global__ void prep_fused(const float* __restrict__ X, const float* __restrict__ W) {
    __shared__ float t[32][33];
    int tx = threadIdx.x, ty = threadIdx.y;   // 32 x 8
    if (blockIdx.z < Bn) {
        int b = blockIdx.z;
        int bn = blockIdx.y * 32;             // feature (n) tile
        const float* Xb = X + (size_t)b * Nn * Fn;
        __half* Xtb = Xt_g + (size_t)b * Fn * Nn;
#pragma unroll
        for (int it = 0; it < 4; it++) {
            int bk = blockIdx.x * 128 + it * 32;   // node (k) subtile
#pragma unroll
            for (int i = 0; i < 4; i++)
                t[ty + i * 8][tx] = Xb[(size_t)(bk + ty + i * 8) * Fn + bn + tx];
            __syncthreads();
#pragma unroll
            for (int i = 0; i < 4; i++)
                Xtb[(size_t)(bn + ty + i * 8) * Nn + bk + tx] =
                    __float2half_rn(t[tx][ty + i * 8]);
            __syncthreads();
        }
    } else {
        if (blockIdx.x != 0) return;
        int bn = blockIdx.y * 32;
#pragma unroll
        for (int it = 0; it < 4; it++) {
            int bk = it * 32;
#pragma unroll
            for (int i = 0; i < 4; i++)
                t[ty + i * 8][tx] = W[(size_t)(bk + ty + i * 8) * Fn + bn + tx];
            __syncthreads();
#pragma unroll
            for (int i = 0; i < 4; i++)
                Wt_g[(size_t)(bn + ty + i * 8) * Fn + bk + tx] =
                    __float2half_rn(t[tx][ty + i * 8]);
            __syncthreads();
        }
    }
}

// ===================== main kernel (R7 verbatim) =====================
__global__ __launch_bounds__(NTHR, 1)
void graphconv_mma_kernel(const float* __restrict__ A,
                          const float* __restrict__ X,
                          float* __restrict__ out)
{
    extern __shared__ char smem[];
    const uint32_t sb = smem_u32(smem);
    const int tid = threadIdx.x;
    const int w = tid >> 5, L = tid & 31;
    const int b = blockIdx.y, r0 = blockIdx.x * 128;

    // warp tile m32 x n32 ; warps 4(m) x 4(n)
    const int mw = (w >> 2) * 32;
    const int nw = (w & 3) * 32;
    const int g = L >> 2, tg = L & 3;
    // ldsm lane offsets (fp16, 128B rows)
    const int arow = L & 15;
    const int achk = (L >> 4) * 16;
    const int brow = (L & 7) + ((L >> 4) << 3);
    const int bchk = ((L >> 3) & 1) * 16;
    // A gmem load role: 16 threads per 256B f32 row, 16B each; 4 rows/thread
    const int lrow = tid >> 4;    // 0..31 (+32i)
    const int lcol = tid & 15;

    const float* Abase = A + ((size_t)b * Nn + r0) * Nn;
    const __half* Xth  = Xt_g + (size_t)b * Fn * Nn;

    float acc[8][4];
#pragma unroll
    for (int i = 0; i < 8; i++)
#pragma unroll
        for (int j = 0; j < 4; j++) acc[i][j] = 0.0f;

    float dega[4] = {0, 0, 0, 0};
    float4 aq[4];                 // A prefetch, 1 tile, 4 rows/thread
    const float* Aldg = Abase + (size_t)lrow * Nn + lcol * 4;

    auto ldgA = [&](int t) {
#pragma unroll
        for (int i = 0; i < 4; i++)
            aq[i] = *(const float4*)(Aldg + (size_t)(32 * i) * Nn + t * KT);
    };
    auto stsA = [&](int buf) {
        uint32_t base = sb + AB_OFF + buf * 16384;
#pragma unroll
        for (int i = 0; i < 4; i++) {
            float4 q = aq[i];
            dega[i] += (q.x + q.y) + (q.z + q.w);
            uint32_t d = base + SW((lrow + 32 * i) * 128 + lcol * 8);
            asm volatile("st.shared.v2.b32 [%0], {%1,%2};"
                :: "r"(d), "r"(packh2(q.x, q.y)), "r"(packh2(q.z, q.w)) : "memory");
        }
    };
    auto cpB = [&](int t) {
        const int s = t & (BSTAGES - 1);
        const int k0 = t * KT;
#pragma unroll
        for (int i = 0; i < 2; i++) {
            int c = tid + i * NTHR;     // 0..1023
            int n = c >> 3, j = c & 7;
            cp16(sb + BS_OFF + s * 16384 + SW(n * 128 + j * 16),
                 Xth + (size_t)n * Nn + k0 + j * 8);
        }
    };
    // warp's m32 x n32 tile over 64 k (4 x k16)
    auto compute64 = [&](uint32_t aA, uint32_t aB, float (*ac)[4]) {
#pragma unroll
        for (int kc = 0; kc < 4; kc++) {
            const int koff = kc * 32;
            uint32_t af[2][4];
#pragma unroll
            for (int mt = 0; mt < 2; mt++)
                ldsm4(af[mt], aA + SW((mw + mt * 16 + arow) * 128 + koff + achk));
            uint32_t bf[4][2];
#pragma unroll
            for (int np = 0; np < 2; np++) {
                uint32_t r[4];
                ldsm4(r, aB + SW((nw + np * 16 + brow) * 128 + koff + bchk));
                bf[np * 2][0] = r[0]; bf[np * 2][1] = r[1];
                bf[np * 2 + 1][0] = r[2]; bf[np * 2 + 1][1] = r[3];
            }
#pragma unroll
            for (int mt = 0; mt < 2; mt++)
#pragma unroll
                for (int nt = 0; nt < 4; nt++)
                    mma16(ac[mt * 4 + nt], af[mt], bf[nt]);
        }
    };

    // ---- prologue ----
    ldgA(0);
#pragma unroll
    for (int t = 0; t < BSTAGES - 1; t++) {
        cpB(t);
        asm volatile("cp.async.commit_group;" ::: "memory");
    }

    // ---- mainloop: 64 tiles, one barrier each ----
    for (int t = 0; t < NTILES; t++) {
        stsA(t & 1);
        if (t + 1 < NTILES) ldgA(t + 1);
        asm volatile("cp.async.wait_group %0;" :: "n"(BSTAGES - 2) : "memory");
        __syncthreads();
        if (t + BSTAGES - 1 < NTILES) cpB(t + BSTAGES - 1);
        asm volatile("cp.async.commit_group;" ::: "memory");
        compute64(sb + AB_OFF + (t & 1) * 16384,
                  sb + BS_OFF + (t & (BSTAGES - 1)) * 16384, acc);
    }

    // ---- deg partials + stage W^T (into freed B stages 0-1) ----
    float* degp = (float*)(smem + DEG_OFF);   // [128 rows][16 chunks]
#pragma unroll
    for (int i = 0; i < 4; i++)
        degp[(lrow + 32 * i) * 16 + lcol] = dega[i];
#pragma unroll
    for (int i = 0; i < 4; i++) {
        int c = tid + i * NTHR;         // 0..2047 chunks of 8 halves
        int n = c >> 4, j = c & 15, kt = j >> 3, jj = j & 7;
        cp16(sb + WS_OFF + kt * 16384 + SW(n * 128 + jj * 16),
             Wt_g + (size_t)n * Fn + j * 8);
    }
    asm volatile("cp.async.commit_group;" ::: "memory");
    __syncthreads();   // all compute done (Ys/A region free), degp visible

    // ---- y = (ax + X) / (deg + 1) -> fp16 smem [2 ktiles][128m][64k] ----
#pragma unroll
    for (int mt = 0; mt < 2; mt++) {
        int m1 = mw + mt * 16 + g, m2 = m1 + 8;
        float s1 = 0.0f, s2 = 0.0f;
#pragma unroll
        for (int j = 0; j < 16; j++) { s1 += degp[m1 * 16 + j]; s2 += degp[m2 * 16 + j]; }
        float r1 = 1.0f / (s1 + 1.0f);
        float r2 = 1.0f / (s2 + 1.0f);
        const float* x1 = X + ((size_t)b * Nn + r0 + m1) * Fn;
        const float* x2 = X + ((size_t)b * Nn + r0 + m2) * Fn;
#pragma unroll
        for (int nt = 0; nt < 4; nt++) {
            int n = nw + nt * 8 + 2 * tg;
            float* c = acc[mt * 4 + nt];
            float2 xa = *(const float2*)(x1 + n);
            float2 xb = *(const float2*)(x2 + n);
            uint32_t y01 = packh2((c[0] + xa.x) * r1, (c[1] + xa.y) * r1);
            uint32_t y23 = packh2((c[2] + xb.x) * r2, (c[3] + xb.y) * r2);
            uint32_t base = sb + YS_OFF + (n >> 6) * 16384;
            asm volatile("st.shared.b32 [%0], %1;"
                         :: "r"(base + SW(m1 * 128 + (n & 63) * 2)), "r"(y01) : "memory");
            asm volatile("st.shared.b32 [%0], %1;"
                         :: "r"(base + SW(m2 * 128 + (n & 63) * 2)), "r"(y23) : "memory");
        }
    }
    asm volatile("cp.async.wait_group 0;" ::: "memory");
    __syncthreads();

    // ---- second GEMM: z = y @ W (M=128,N=128,K=128) ----
    float acc2[8][4];
#pragma unroll
    for (int i = 0; i < 8; i++)
#pragma unroll
        for (int j = 0; j < 4; j++) acc2[i][j] = 0.0f;
#pragma unroll
    for (int kt = 0; kt < 2; kt++)
        compute64(sb + YS_OFF + kt * 16384, sb + WS_OFF + kt * 16384, acc2);

    // ---- relu + store ----
#pragma unroll
    for (int mt = 0; mt < 2; mt++) {
        int m1 = mw + mt * 16 + g, m2 = m1 + 8;
        float* o1 = out + ((size_t)b * Nn + r0 + m1) * Fn;
        float* o2 = out + ((size_t)b * Nn + r0 + m2) * Fn;
#pragma unroll
        for (int nt = 0; nt < 4; nt++) {
            int n = nw + nt * 8 + 2 * tg;
            float* c = acc2[mt * 4 + nt];
            *(float2*)(o1 + n) = make_float2(fmaxf(c[0], 0.0f), fmaxf(c[1], 0.0f));
            *(float2*)(o2 + n) = make_float2(fmaxf(c[2], 0.0f), fmaxf(c[3], 0.0f));
        }
    }
}

// ===================== launch =====================
extern "C" void kernel_launch(void* const* d_in, const int* in_sizes, int n_in,
                              void* d_out, int out_size)
{
    const float* A = (const float*)d_in[0];
    const float* X = (const float*)d_in[1];
    const float* W = (const float*)d_in[2];
    float* out = (float*)d_out;

    static bool attr_set = false;
    if (!attr_set) {
        cudaFuncSetAttribute(graphconv_mma_kernel,
                             cudaFuncAttributeMaxDynamicSharedMemorySize, SMEM_TOTAL);
        attr_set = true;
    }

    dim3 tb(32, 8);
    prep_fused<<<dim3(Nn / 128, Fn / 32, Bn + 1), tb>>>(X, W);

    dim3 grid(Nn / 128, Bn);
    graphconv_mma_kernel<<<grid, NTHR, SMEM_TOTAL>>>(A, X, out);
}